// round 6
// baseline (speedup 1.0000x reference)
#include <cuda_runtime.h>
#include <cuda_bf16.h>
#include <math.h>

// RecognitionODERNN: B=256, T=96, OBS=64, LATENT=256, HID=512, N_SUB=3
//
// Persistent batch-split kernel: 64 CTAs x 256 threads, 4 batch rows per CTA.
// The whole 95-step reverse-time scan runs inside one launch; the only
// synchronization is __syncthreads (2 per MLP eval). Activations are kept in
// shared memory transposed as float4-per-column (one broadcast LDS.128 yields
// the value for all 4 batch rows). Weights stream from L2 (fully L2-resident).

#define BATCH  256
#define TSEQ   96
#define OBSD   64
#define LAT    256
#define HIDD   512
#define ROWS   4
#define TPB    256
#define NCTA   (BATCH / ROWS)   // 64

// ---------------------------------------------------------------------------
// Phase A of latent_ode MLP: hid = tanh(in @ W1 + b1)
// in: [LAT] float4 (transposed activations, .x..*.w = rows 0..3)
// Each thread computes 2 hidden columns (c0 = 2*tid, c0+1) for all 4 rows.
// ---------------------------------------------------------------------------
__device__ __forceinline__ void mlp_in_ode(const float4* __restrict__ in,
                                           const float*  __restrict__ W1,
                                           float b1a, float b1b,
                                           float4* __restrict__ hid, int t)
{
    const int c0 = 2 * t;
    float u0 = b1a, u1 = b1a, u2 = b1a, u3 = b1a;
    float v0 = b1b, v1 = b1b, v2 = b1b, v3 = b1b;
    const float2* __restrict__ wp =
        reinterpret_cast<const float2*>(W1) + t;   // element c0/2 of row 0
#pragma unroll 4
    for (int k = 0; k < LAT; ++k) {
        float4 a = in[k];
        float2 w = wp[k * (HIDD / 2)];
        u0 = fmaf(a.x, w.x, u0); u1 = fmaf(a.y, w.x, u1);
        u2 = fmaf(a.z, w.x, u2); u3 = fmaf(a.w, w.x, u3);
        v0 = fmaf(a.x, w.y, v0); v1 = fmaf(a.y, w.y, v1);
        v2 = fmaf(a.z, w.y, v2); v3 = fmaf(a.w, w.y, v3);
    }
    hid[c0]     = make_float4(tanhf(u0), tanhf(u1), tanhf(u2), tanhf(u3));
    hid[c0 + 1] = make_float4(tanhf(v0), tanhf(v1), tanhf(v2), tanhf(v3));
}

// ---------------------------------------------------------------------------
// Phase A of the RNN MLP: hid = tanh(concat(s, x) @ Wr1 + br1)
// s: [LAT] float4, x: [OBSD] float4. Wr1 is [(LAT+OBSD), HIDD] row-major.
// ---------------------------------------------------------------------------
__device__ __forceinline__ void mlp_in_rnn(const float4* __restrict__ s,
                                           const float4* __restrict__ x,
                                           const float*  __restrict__ Wr1,
                                           float b1a, float b1b,
                                           float4* __restrict__ hid, int t)
{
    const int c0 = 2 * t;
    float u0 = b1a, u1 = b1a, u2 = b1a, u3 = b1a;
    float v0 = b1b, v1 = b1b, v2 = b1b, v3 = b1b;
    const float2* __restrict__ wp =
        reinterpret_cast<const float2*>(Wr1) + t;
#pragma unroll 4
    for (int k = 0; k < LAT; ++k) {
        float4 a = s[k];
        float2 w = wp[k * (HIDD / 2)];
        u0 = fmaf(a.x, w.x, u0); u1 = fmaf(a.y, w.x, u1);
        u2 = fmaf(a.z, w.x, u2); u3 = fmaf(a.w, w.x, u3);
        v0 = fmaf(a.x, w.y, v0); v1 = fmaf(a.y, w.y, v1);
        v2 = fmaf(a.z, w.y, v2); v3 = fmaf(a.w, w.y, v3);
    }
#pragma unroll 4
    for (int k = 0; k < OBSD; ++k) {
        float4 a = x[k];
        float2 w = wp[(LAT + k) * (HIDD / 2)];
        u0 = fmaf(a.x, w.x, u0); u1 = fmaf(a.y, w.x, u1);
        u2 = fmaf(a.z, w.x, u2); u3 = fmaf(a.w, w.x, u3);
        v0 = fmaf(a.x, w.y, v0); v1 = fmaf(a.y, w.y, v1);
        v2 = fmaf(a.z, w.y, v2); v3 = fmaf(a.w, w.y, v3);
    }
    hid[c0]     = make_float4(tanhf(u0), tanhf(u1), tanhf(u2), tanhf(u3));
    hid[c0 + 1] = make_float4(tanhf(v0), tanhf(v1), tanhf(v2), tanhf(v3));
}

// ---------------------------------------------------------------------------
// Phase B: out[:, t] = hid @ W2[:, t] + bias   (one output column per thread,
// all 4 rows). Returns the column in registers.
// ---------------------------------------------------------------------------
__device__ __forceinline__ float4 mlp_out(const float*  __restrict__ W2,
                                          float bias,
                                          const float4* __restrict__ hid, int t)
{
    float a0 = bias, a1 = bias, a2 = bias, a3 = bias;
#pragma unroll 8
    for (int k = 0; k < HIDD; ++k) {
        float4 h = hid[k];
        float  w = W2[k * LAT + t];
        a0 = fmaf(h.x, w, a0); a1 = fmaf(h.y, w, a1);
        a2 = fmaf(h.z, w, a2); a3 = fmaf(h.w, w, a3);
    }
    return make_float4(a0, a1, a2, a3);
}

// ---------------------------------------------------------------------------
// Main persistent kernel
// ---------------------------------------------------------------------------
__global__ void __launch_bounds__(TPB, 1)
odernn_kernel(const float* __restrict__ dataset,    // [B, T, OBS]
              const float* __restrict__ timestamps, // [B, T]
              const float* __restrict__ W1,  const float* __restrict__ b1,
              const float* __restrict__ W2,  const float* __restrict__ b2,
              const float* __restrict__ Wr1, const float* __restrict__ br1,
              const float* __restrict__ Wr2, const float* __restrict__ br2,
              float* __restrict__ out)               // [B, LAT]
{
    __shared__ float4 sS[LAT];     // state (transposed, rows 0..3 in xyzw)
    __shared__ float4 sTmp[LAT];   // RK4 evaluation point
    __shared__ float4 sHid[HIDD];  // hidden activations
    __shared__ float4 sX[OBSD];    // current observation
    __shared__ float  sH[ROWS];    // per-row substep size h

    const int t    = threadIdx.x;
    const int row0 = blockIdx.x * ROWS;

    // Preload per-thread bias constants (invariant across the whole scan)
    const float b1a  = b1[2 * t],  b1b  = b1[2 * t + 1];
    const float b2s  = b2[t];
    const float br1a = br1[2 * t], br1b = br1[2 * t + 1];
    const float br2s = br2[t];

    // ---- init: state = 0, load x = dataset[:, T-1] ----
    sS[t] = make_float4(0.f, 0.f, 0.f, 0.f);
    {
        const int c = t & (OBSD - 1);
        const int r = t >> 6;                      // 256 threads / 64 cols = 4 rows
        float v = dataset[((row0 + r) * TSEQ + (TSEQ - 1)) * OBSD + c];
        reinterpret_cast<float*>(&sX[c])[r] = v;
    }
    __syncthreads();

    // ---- initial RNN update: s += rnn(concat(s, x_{T-1})) ----
    mlp_in_rnn(sS, sX, Wr1, br1a, br1b, sHid, t);
    __syncthreads();
    {
        float4 o  = mlp_out(Wr2, br2s, sHid, t);
        float4 sv = sS[t];
        sS[t] = make_float4(sv.x + o.x, sv.y + o.y, sv.z + o.z, sv.w + o.w);
    }
    __syncthreads();

    // ---- reverse-time scan: i = T-2 .. 0 ----
    for (int i = TSEQ - 2; i >= 0; --i) {
        // per-row substep size h = (ts[i] - ts[i+1]) / 3
        if (t < ROWS) {
            const float* tsr = timestamps + (row0 + t) * TSEQ;
            sH[t] = (tsr[i] - tsr[i + 1]) / 3.0f;
        }
        // load x_i
        {
            const int c = t & (OBSD - 1);
            const int r = t >> 6;
            float v = dataset[((row0 + r) * TSEQ + i) * OBSD + c];
            reinterpret_cast<float*>(&sX[c])[r] = v;
        }
        __syncthreads();

        const float h0 = sH[0], h1 = sH[1], h2 = sH[2], h3 = sH[3];
        const float q0 = 0.5f * h0, q1 = 0.5f * h1, q2 = 0.5f * h2, q3 = 0.5f * h3;
        const float g0 = h0 / 6.0f, g1 = h1 / 6.0f, g2 = h2 / 6.0f, g3 = h3 / 6.0f;

        // ---- 3 RK4 substeps ----
#pragma unroll 1
        for (int sub = 0; sub < 3; ++sub) {
            float4 sv = sS[t];

            // k1
            mlp_in_ode(sS, W1, b1a, b1b, sHid, t);
            __syncthreads();
            float4 k  = mlp_out(W2, b2s, sHid, t);
            float4 ka = k;
            sTmp[t] = make_float4(fmaf(q0, k.x, sv.x), fmaf(q1, k.y, sv.y),
                                  fmaf(q2, k.z, sv.z), fmaf(q3, k.w, sv.w));
            __syncthreads();

            // k2
            mlp_in_ode(sTmp, W1, b1a, b1b, sHid, t);
            __syncthreads();
            k = mlp_out(W2, b2s, sHid, t);
            ka.x += 2.0f * k.x; ka.y += 2.0f * k.y;
            ka.z += 2.0f * k.z; ka.w += 2.0f * k.w;
            sTmp[t] = make_float4(fmaf(q0, k.x, sv.x), fmaf(q1, k.y, sv.y),
                                  fmaf(q2, k.z, sv.z), fmaf(q3, k.w, sv.w));
            __syncthreads();

            // k3
            mlp_in_ode(sTmp, W1, b1a, b1b, sHid, t);
            __syncthreads();
            k = mlp_out(W2, b2s, sHid, t);
            ka.x += 2.0f * k.x; ka.y += 2.0f * k.y;
            ka.z += 2.0f * k.z; ka.w += 2.0f * k.w;
            sTmp[t] = make_float4(fmaf(h0, k.x, sv.x), fmaf(h1, k.y, sv.y),
                                  fmaf(h2, k.z, sv.z), fmaf(h3, k.w, sv.w));
            __syncthreads();

            // k4 + state update
            mlp_in_ode(sTmp, W1, b1a, b1b, sHid, t);
            __syncthreads();
            k = mlp_out(W2, b2s, sHid, t);
            ka.x += k.x; ka.y += k.y; ka.z += k.z; ka.w += k.w;
            sS[t] = make_float4(fmaf(g0, ka.x, sv.x), fmaf(g1, ka.y, sv.y),
                                fmaf(g2, ka.z, sv.z), fmaf(g3, ka.w, sv.w));
            __syncthreads();
        }

        // ---- RNN update: s += rnn(concat(s, x_i)) ----
        mlp_in_rnn(sS, sX, Wr1, br1a, br1b, sHid, t);
        __syncthreads();
        {
            float4 o  = mlp_out(Wr2, br2s, sHid, t);
            float4 sv = sS[t];
            sS[t] = make_float4(sv.x + o.x, sv.y + o.y, sv.z + o.z, sv.w + o.w);
        }
        __syncthreads();
    }

    // ---- write final state ----
    float4 sv = sS[t];
    out[(row0 + 0) * LAT + t] = sv.x;
    out[(row0 + 1) * LAT + t] = sv.y;
    out[(row0 + 2) * LAT + t] = sv.z;
    out[(row0 + 3) * LAT + t] = sv.w;
}

// ---------------------------------------------------------------------------
extern "C" void kernel_launch(void* const* d_in, const int* in_sizes, int n_in,
                              void* d_out, int out_size)
{
    const float* dataset    = (const float*)d_in[0];
    const float* timestamps = (const float*)d_in[1];
    const float* W1  = (const float*)d_in[2];
    const float* b1  = (const float*)d_in[3];
    const float* W2  = (const float*)d_in[4];
    const float* b2  = (const float*)d_in[5];
    const float* Wr1 = (const float*)d_in[6];
    const float* br1 = (const float*)d_in[7];
    const float* Wr2 = (const float*)d_in[8];
    const float* br2 = (const float*)d_in[9];
    float* out = (float*)d_out;

    odernn_kernel<<<NCTA, TPB>>>(dataset, timestamps,
                                 W1, b1, W2, b2, Wr1, br1, Wr2, br2, out);
}

// round 7
// speedup vs baseline: 1.7837x; 1.7837x over previous
#include <cuda_runtime.h>
#include <cuda_bf16.h>
#include <math.h>

// RecognitionODERNN: B=256, T=96, OBS=64, LATENT=256, HID=512, N_SUB=3
//
// Persistent batch-split kernel: 64 CTAs x 512 threads, 4 batch rows per CTA.
// Whole 95-step reverse scan in one launch; __syncthreads-only sync.
// Activations live in SMEM as packed row-pairs (ulonglong2 = (r0,r1),(r2,r3))
// so one LDS.128 feeds fma.rn.f32x2 (FFMA2) directly. Weights stream from L2.
// Phase A (in->hid, tanh): 1 hidden column per thread (512 cols).
// Phase B (hid->out): 256 cols, K=512 split across two thread halves, SMEM add.

#define TSEQ 96
#define OBSD 64
#define LAT  256
#define HIDD 512
#define ROWS 4
#define TPB  512
#define NCTA 64

typedef unsigned long long u64;

__device__ __forceinline__ u64 pk2(float x, float y) {
    u64 r; asm("mov.b64 %0, {%1, %2};" : "=l"(r) : "f"(x), "f"(y)); return r;
}
__device__ __forceinline__ void up2(u64 p, float &x, float &y) {
    asm("mov.b64 {%0, %1}, %2;" : "=f"(x), "=f"(y) : "l"(p));
}
__device__ __forceinline__ u64 ffma2(u64 a, u64 b, u64 c) {
    u64 d; asm("fma.rn.f32x2 %0, %1, %2, %3;" : "=l"(d) : "l"(a), "l"(b), "l"(c));
    return d;
}
__device__ __forceinline__ u64 fadd2(u64 a, u64 b) {
    u64 d; asm("add.rn.f32x2 %0, %1, %2;" : "=l"(d) : "l"(a), "l"(b)); return d;
}

// acc(pair01, pair23) += sIn[k] * W[k*stride]  for k in [0, n)
__device__ __forceinline__ void dot_seg(const ulonglong2 *__restrict__ sIn, int n,
                                        const float *__restrict__ Wcol, int stride,
                                        u64 &a01, u64 &a23)
{
#pragma unroll 8
    for (int k = 0; k < n; ++k) {
        ulonglong2 a = sIn[k];          // LDS.128: (r0,r1),(r2,r3) packed
        float wk = Wcol[k * stride];    // LDG.32 (L2-resident weight)
        u64 wp = pk2(wk, wk);
        a01 = ffma2(a.x, wp, a01);
        a23 = ffma2(a.y, wp, a23);
    }
}

// One full MLP eval (phase A tanh + phase B). All TPB threads participate.
// Returns output column c=t&255 (rows 0..3) — valid only for threads with half==0.
template <bool HASX>
__device__ __forceinline__ float4 mlp_eval(
    const ulonglong2 *__restrict__ sIn, const ulonglong2 *__restrict__ sXv,
    ulonglong2 *__restrict__ sHid, ulonglong2 *__restrict__ sPart,
    const float *__restrict__ Wa, const float *__restrict__ Wb,
    float ba, float bb, int t, int c, int half, int k0)
{
    // ---- phase A: hid[t] = tanh(in . Wa[:,t] + ba) ----
    u64 a01 = pk2(ba, ba), a23 = a01;
    dot_seg(sIn, LAT, Wa + t, HIDD, a01, a23);
    if (HASX)
        dot_seg(sXv, OBSD, Wa + LAT * HIDD + t, HIDD, a01, a23);
    {
        float u0, u1, u2, u3;
        up2(a01, u0, u1); up2(a23, u2, u3);
        ulonglong2 hv;
        hv.x = pk2(tanhf(u0), tanhf(u1));
        hv.y = pk2(tanhf(u2), tanhf(u3));
        sHid[t] = hv;
    }
    __syncthreads();

    // ---- phase B: out[c] = hid . Wb[:,c] + bb, K split across the 2 halves ----
    u64 o01, o23;
    if (half == 0) { o01 = pk2(bb, bb); o23 = o01; }
    else           { o01 = 0ull;        o23 = 0ull; }
    dot_seg(sHid + k0, HIDD / 2, Wb + k0 * LAT + c, LAT, o01, o23);
    if (half) { ulonglong2 pv; pv.x = o01; pv.y = o23; sPart[c] = pv; }
    __syncthreads();

    float4 r = make_float4(0.f, 0.f, 0.f, 0.f);
    if (!half) {
        ulonglong2 p = sPart[c];
        o01 = fadd2(o01, p.x);
        o23 = fadd2(o23, p.y);
        up2(o01, r.x, r.y);
        up2(o23, r.z, r.w);
    }
    return r;
}

__global__ void __launch_bounds__(TPB, 1)
odernn_kernel(const float *__restrict__ dataset,    // [B, T, OBS]
              const float *__restrict__ timestamps, // [B, T]
              const float *__restrict__ W1,  const float *__restrict__ b1,
              const float *__restrict__ W2,  const float *__restrict__ b2,
              const float *__restrict__ Wr1, const float *__restrict__ br1,
              const float *__restrict__ Wr2, const float *__restrict__ br2,
              float *__restrict__ out)               // [B, LAT]
{
    __shared__ ulonglong2 sS[LAT];     // state, packed row-pairs
    __shared__ ulonglong2 sTmp[LAT];   // RK4 eval point
    __shared__ ulonglong2 sHid[HIDD];  // hidden activations
    __shared__ ulonglong2 sX[OBSD];    // current observation
    __shared__ ulonglong2 sPart[LAT];  // phase-B partials (upper K half)
    __shared__ float      sH[ROWS];    // per-row substep size

    const int t    = threadIdx.x;
    const int c    = t & (LAT - 1);
    const int half = t >> 8;             // 0: K[0,256), 1: K[256,512)
    const int k0   = half * (HIDD / 2);
    const int row0 = blockIdx.x * ROWS;

    const float b1c  = b1[t];
    const float br1c = br1[t];
    const float b2c  = b2[c];
    const float br2c = br2[c];

    // ---- init: state = 0, x = dataset[:, T-1] ----
    if (t < LAT) { ulonglong2 z; z.x = 0ull; z.y = 0ull; sS[t] = z; }
    if (t < 2 * OBSD) {
        const int cc = t & (OBSD - 1);
        const int pr = t >> 6;                 // 0 -> rows(0,1), 1 -> rows(2,3)
        const int r0 = row0 + 2 * pr;
        float x0 = dataset[(r0 * TSEQ + (TSEQ - 1)) * OBSD + cc];
        float x1 = dataset[((r0 + 1) * TSEQ + (TSEQ - 1)) * OBSD + cc];
        ((u64 *)sX)[cc * 2 + pr] = pk2(x0, x1);
    }
    __syncthreads();

    // ---- initial RNN update ----
    {
        float4 o = mlp_eval<true>(sS, sX, sHid, sPart, Wr1, Wr2, br1c, br2c,
                                  t, c, half, k0);
        if (!half) {
            float s0, s1, s2, s3;
            ulonglong2 sv = sS[c];
            up2(sv.x, s0, s1); up2(sv.y, s2, s3);
            ulonglong2 nv;
            nv.x = pk2(s0 + o.x, s1 + o.y);
            nv.y = pk2(s2 + o.z, s3 + o.w);
            sS[c] = nv;
        }
        __syncthreads();
    }

    // ---- reverse-time scan: i = T-2 .. 0 ----
    for (int i = TSEQ - 2; i >= 0; --i) {
        if (t < 2 * OBSD) {
            const int cc = t & (OBSD - 1);
            const int pr = t >> 6;
            const int r0 = row0 + 2 * pr;
            float x0 = dataset[(r0 * TSEQ + i) * OBSD + cc];
            float x1 = dataset[((r0 + 1) * TSEQ + i) * OBSD + cc];
            ((u64 *)sX)[cc * 2 + pr] = pk2(x0, x1);
        }
        if (t < ROWS) {
            const float *tsr = timestamps + (row0 + t) * TSEQ;
            sH[t] = (tsr[i] - tsr[i + 1]) / 3.0f;
        }
        __syncthreads();

        const float h0 = sH[0], h1 = sH[1], h2 = sH[2], h3 = sH[3];
        const float q0 = 0.5f * h0, q1 = 0.5f * h1, q2 = 0.5f * h2, q3 = 0.5f * h3;
        const float g0 = h0 / 6.0f, g1 = h1 / 6.0f, g2 = h2 / 6.0f, g3 = h3 / 6.0f;

        // ---- 3 RK4 substeps ----
#pragma unroll 1
        for (int sub = 0; sub < 3; ++sub) {
            float s0 = 0.f, s1 = 0.f, s2 = 0.f, s3 = 0.f;
            if (!half) {
                ulonglong2 sv = sS[c];
                up2(sv.x, s0, s1); up2(sv.y, s2, s3);
            }
            float a0 = 0.f, a1 = 0.f, a2 = 0.f, a3 = 0.f;

            // k1
            float4 k = mlp_eval<false>(sS, sX, sHid, sPart, W1, W2, b1c, b2c,
                                       t, c, half, k0);
            if (!half) {
                a0 = k.x; a1 = k.y; a2 = k.z; a3 = k.w;
                ulonglong2 v;
                v.x = pk2(fmaf(q0, k.x, s0), fmaf(q1, k.y, s1));
                v.y = pk2(fmaf(q2, k.z, s2), fmaf(q3, k.w, s3));
                sTmp[c] = v;
            }
            __syncthreads();

            // k2
            k = mlp_eval<false>(sTmp, sX, sHid, sPart, W1, W2, b1c, b2c,
                                t, c, half, k0);
            if (!half) {
                a0 += 2.0f * k.x; a1 += 2.0f * k.y;
                a2 += 2.0f * k.z; a3 += 2.0f * k.w;
                ulonglong2 v;
                v.x = pk2(fmaf(q0, k.x, s0), fmaf(q1, k.y, s1));
                v.y = pk2(fmaf(q2, k.z, s2), fmaf(q3, k.w, s3));
                sTmp[c] = v;
            }
            __syncthreads();

            // k3
            k = mlp_eval<false>(sTmp, sX, sHid, sPart, W1, W2, b1c, b2c,
                                t, c, half, k0);
            if (!half) {
                a0 += 2.0f * k.x; a1 += 2.0f * k.y;
                a2 += 2.0f * k.z; a3 += 2.0f * k.w;
                ulonglong2 v;
                v.x = pk2(fmaf(h0, k.x, s0), fmaf(h1, k.y, s1));
                v.y = pk2(fmaf(h2, k.z, s2), fmaf(h3, k.w, s3));
                sTmp[c] = v;
            }
            __syncthreads();

            // k4 + state update
            k = mlp_eval<false>(sTmp, sX, sHid, sPart, W1, W2, b1c, b2c,
                                t, c, half, k0);
            if (!half) {
                a0 += k.x; a1 += k.y; a2 += k.z; a3 += k.w;
                ulonglong2 v;
                v.x = pk2(fmaf(g0, a0, s0), fmaf(g1, a1, s1));
                v.y = pk2(fmaf(g2, a2, s2), fmaf(g3, a3, s3));
                sS[c] = v;
            }
            __syncthreads();
        }

        // ---- RNN update: s += rnn(concat(s, x_i)) ----
        {
            float4 o = mlp_eval<true>(sS, sX, sHid, sPart, Wr1, Wr2, br1c, br2c,
                                      t, c, half, k0);
            if (!half) {
                float s0, s1, s2, s3;
                ulonglong2 sv = sS[c];
                up2(sv.x, s0, s1); up2(sv.y, s2, s3);
                ulonglong2 nv;
                nv.x = pk2(s0 + o.x, s1 + o.y);
                nv.y = pk2(s2 + o.z, s3 + o.w);
                sS[c] = nv;
            }
            __syncthreads();
        }
    }

    // ---- write final state ----
    if (!half) {
        ulonglong2 sv = sS[c];
        float s0, s1, s2, s3;
        up2(sv.x, s0, s1); up2(sv.y, s2, s3);
        out[(row0 + 0) * LAT + c] = s0;
        out[(row0 + 1) * LAT + c] = s1;
        out[(row0 + 2) * LAT + c] = s2;
        out[(row0 + 3) * LAT + c] = s3;
    }
}

// ---------------------------------------------------------------------------
extern "C" void kernel_launch(void* const* d_in, const int* in_sizes, int n_in,
                              void* d_out, int out_size)
{
    (void)in_sizes; (void)n_in; (void)out_size;
    const float* dataset    = (const float*)d_in[0];
    const float* timestamps = (const float*)d_in[1];
    const float* W1  = (const float*)d_in[2];
    const float* b1  = (const float*)d_in[3];
    const float* W2  = (const float*)d_in[4];
    const float* b2  = (const float*)d_in[5];
    const float* Wr1 = (const float*)d_in[6];
    const float* br1 = (const float*)d_in[7];
    const float* Wr2 = (const float*)d_in[8];
    const float* br2 = (const float*)d_in[9];
    float* out = (float*)d_out;

    odernn_kernel<<<NCTA, TPB>>>(dataset, timestamps,
                                 W1, b1, W2, b2, Wr1, br1, Wr2, br2, out);
}

// round 9
// speedup vs baseline: 2.3992x; 1.3450x over previous
#include <cuda_runtime.h>
#include <cuda_bf16.h>
#include <math.h>

// RecognitionODERNN: B=256, T=96, OBS=64, LATENT=256, HID=512, N_SUB=3
//
// 64 CTAs x 512 threads, 4 batch rows/CTA, whole scan in one launch.
// Inner GEMM: each thread owns a 4-column group over a K-slice.
//   - activations in SMEM as duplicated pairs (v,v): LDS.128 = 2 packed rows
//   - weights via LDG.128 = 4 cols = 2 packed fma.rn.f32x2 operands
//   - 11 issues / 16 MACs
// K-slice partials combined via SMEM. state+obs live in one contiguous
// 320-entry buffer so the RNN concat layer is a plain K=320 loop.

#define TSEQ 96
#define OBSD 64
#define LAT  256
#define HIDD 512
#define KRNN (LAT + OBSD)   // 320
#define ROWS 4
#define TPB  512
#define NCTA 64

typedef unsigned long long u64;

struct dup4 { ulonglong2 lo, hi; };   // (r0,r0),(r1,r1),(r2,r2),(r3,r3)

__device__ __forceinline__ u64 pk2(float x, float y) {
    u64 r; asm("mov.b64 %0, {%1, %2};" : "=l"(r) : "f"(x), "f"(y)); return r;
}
__device__ __forceinline__ void up2(u64 p, float &x, float &y) {
    asm("mov.b64 {%0, %1}, %2;" : "=f"(x), "=f"(y) : "l"(p));
}
__device__ __forceinline__ float lo2(u64 p) {
    float x, y; up2(p, x, y); return x;
}
__device__ __forceinline__ u64 ffma2(u64 a, u64 b, u64 c) {
    u64 d; asm("fma.rn.f32x2 %0, %1, %2, %3;" : "=l"(d) : "l"(a), "l"(b), "l"(c));
    return d;
}
__device__ __forceinline__ u64 fadd2(u64 a, u64 b) {
    u64 d; asm("add.rn.f32x2 %0, %1, %2;" : "=l"(d) : "l"(a), "l"(b)); return d;
}

// ---------------------------------------------------------------------------
// One GEMM phase: thread computes 4 output columns [c0, c0+4) over K-slice s.
// ---------------------------------------------------------------------------
template <int KSPAN, int WSTRIDE, int NC>
__device__ __forceinline__ void gemm_slice(const dup4 *__restrict__ in,
                                           const float *__restrict__ W,
                                           ulonglong2 *__restrict__ sPart,
                                           int s, int c0)
{
    const dup4 *ip = in + s * KSPAN;
    const float *wp = W + (size_t)(s * KSPAN) * WSTRIDE + c0;

    u64 a0 = 0, a1 = 0, a2 = 0, a3 = 0;   // cols (c0, c0+1), rows 0..3
    u64 b0 = 0, b1 = 0, b2 = 0, b3 = 0;   // cols (c0+2, c0+3), rows 0..3
#pragma unroll 4
    for (int k = 0; k < KSPAN; ++k) {
        dup4 a = ip[k];                                    // 2x LDS.128 bcast
        ulonglong2 w = *reinterpret_cast<const ulonglong2 *>(wp + (size_t)k * WSTRIDE);
        a0 = ffma2(a.lo.x, w.x, a0);  b0 = ffma2(a.lo.x, w.y, b0);
        a1 = ffma2(a.lo.y, w.x, a1);  b1 = ffma2(a.lo.y, w.y, b1);
        a2 = ffma2(a.hi.x, w.x, a2);  b2 = ffma2(a.hi.x, w.y, b2);
        a3 = ffma2(a.hi.y, w.x, a3);  b3 = ffma2(a.hi.y, w.y, b3);
    }
    // transpose 4x4 to per-column ((r0,r1),(r2,r3)) and store
    float f00, f01, f10, f11, f20, f21, f30, f31;
    float g00, g01, g10, g11, g20, g21, g30, g31;
    up2(a0, f00, f01); up2(a1, f10, f11); up2(a2, f20, f21); up2(a3, f30, f31);
    up2(b0, g00, g01); up2(b1, g10, g11); up2(b2, g20, g21); up2(b3, g30, g31);
    ulonglong2 v;
    v.x = pk2(f00, f10); v.y = pk2(f20, f30); sPart[s * NC + c0 + 0] = v;
    v.x = pk2(f01, f11); v.y = pk2(f21, f31); sPart[s * NC + c0 + 1] = v;
    v.x = pk2(g00, g10); v.y = pk2(g20, g30); sPart[s * NC + c0 + 2] = v;
    v.x = pk2(g01, g11); v.y = pk2(g21, g31); sPart[s * NC + c0 + 3] = v;
}

// Sum NS partial slices for column c -> ((r0,r1),(r2,r3)) + bias
template <int NS, int NC>
__device__ __forceinline__ ulonglong2 combine(const ulonglong2 *__restrict__ sPart,
                                              int c, float bias)
{
    ulonglong2 p0 = sPart[c];
    u64 sx = p0.x, sy = p0.y;
#pragma unroll
    for (int s = 1; s < NS; ++s) {
        ulonglong2 p = sPart[s * NC + c];
        sx = fadd2(sx, p.x);
        sy = fadd2(sy, p.y);
    }
    u64 bb = pk2(bias, bias);
    ulonglong2 r; r.x = fadd2(sx, bb); r.y = fadd2(sy, bb);
    return r;
}

__device__ __forceinline__ void store_dup(dup4 *dst, float v0, float v1,
                                          float v2, float v3)
{
    dup4 d;
    d.lo.x = pk2(v0, v0); d.lo.y = pk2(v1, v1);
    d.hi.x = pk2(v2, v2); d.hi.y = pk2(v3, v3);
    *dst = d;
}

// ---------------------------------------------------------------------------
// One full MLP eval: phase A (K = KSA*4, tanh) then phase B (K = 512).
// Returns output column t (rows 0..3) for t < LAT; zeros otherwise.
// All TPB threads must call this (it contains __syncthreads).
// ---------------------------------------------------------------------------
template <int KSA>
__device__ __forceinline__ float4 mlp_eval(
    const dup4 *__restrict__ in,
    const float *__restrict__ Wa, float ba,
    const float *__restrict__ Wb, float bb,
    dup4 *__restrict__ sHid, ulonglong2 *__restrict__ sPart,
    int t, int sA, int cA, int sB, int cB)
{
    gemm_slice<KSA, HIDD, HIDD>(in, Wa, sPart, sA, cA);
    __syncthreads();
    {   // combine A + tanh -> sHid (all 512 threads, column t)
        ulonglong2 hsum = combine<4, HIDD>(sPart, t, ba);
        float u0, u1, u2, u3;
        up2(hsum.x, u0, u1); up2(hsum.y, u2, u3);
        store_dup(&sHid[t], tanhf(u0), tanhf(u1), tanhf(u2), tanhf(u3));
    }
    __syncthreads();
    gemm_slice<HIDD / 8, LAT, LAT>(sHid, Wb, sPart, sB, cB);
    __syncthreads();
    float4 res = make_float4(0.f, 0.f, 0.f, 0.f);
    if (t < LAT) {
        ulonglong2 osum = combine<8, LAT>(sPart, t, bb);
        up2(osum.x, res.x, res.y);
        up2(osum.y, res.z, res.w);
    }
    return res;
}

// ---------------------------------------------------------------------------
__global__ void __launch_bounds__(TPB, 1)
odernn_kernel(const float *__restrict__ dataset,    // [B, T, OBS]
              const float *__restrict__ timestamps, // [B, T]
              const float *__restrict__ W1,  const float *__restrict__ b1,
              const float *__restrict__ W2,  const float *__restrict__ b2,
              const float *__restrict__ Wr1, const float *__restrict__ br1,
              const float *__restrict__ Wr2, const float *__restrict__ br2,
              float *__restrict__ out)               // [B, LAT]
{
    extern __shared__ char smem[];
    dup4       *sC    = reinterpret_cast<dup4 *>(smem);                 // [320] state+obs
    dup4       *sTmp  = sC + KRNN;                                      // [256]
    dup4       *sHid  = sTmp + LAT;                                     // [512]
    ulonglong2 *sPart = reinterpret_cast<ulonglong2 *>(sHid + HIDD);    // [2048]
    float      *sH    = reinterpret_cast<float *>(sPart + 2048);        // [4]

    const int t    = threadIdx.x;
    const int row0 = blockIdx.x * ROWS;

    // phase-A mapping: 4 slices x 128 col-groups
    const int sA = t >> 7, cA = 4 * (t & 127);
    // phase-B mapping: 8 slices x 64 col-groups
    const int sB = t >> 6, cB = 4 * (t & 63);

    const float b1c  = b1[t];
    const float br1c = br1[t];
    const float b2c  = (t < LAT) ? b2[t]  : 0.f;
    const float br2c = (t < LAT) ? br2[t] : 0.f;

    // ---- init: state = 0; load x = dataset[:, T-1] ----
    if (t < LAT) store_dup(&sC[t], 0.f, 0.f, 0.f, 0.f);
    if (t < LAT) {
        const int cc = t & (OBSD - 1);
        const int r  = t >> 6;
        float v = dataset[((row0 + r) * TSEQ + (TSEQ - 1)) * OBSD + cc];
        reinterpret_cast<u64 *>(&sC[LAT + cc])[r] = pk2(v, v);
    }
    __syncthreads();

    // ---- initial RNN update: s += rnn(concat(s, x_{T-1})) ----
    {
        float4 o = mlp_eval<KRNN / 4>(sC, Wr1, br1c, Wr2, br2c,
                                      sHid, sPart, t, sA, cA, sB, cB);
        if (t < LAT) {
            dup4 d = sC[t];
            store_dup(&sC[t], lo2(d.lo.x) + o.x, lo2(d.lo.y) + o.y,
                              lo2(d.hi.x) + o.z, lo2(d.hi.y) + o.w);
        }
        __syncthreads();
    }

    // ---- reverse-time scan: i = T-2 .. 0 ----
    for (int i = TSEQ - 2; i >= 0; --i) {
        if (t < LAT) {
            const int cc = t & (OBSD - 1);
            const int r  = t >> 6;
            float v = dataset[((row0 + r) * TSEQ + i) * OBSD + cc];
            reinterpret_cast<u64 *>(&sC[LAT + cc])[r] = pk2(v, v);
        }
        if (t < ROWS) {
            const float *tsr = timestamps + (row0 + t) * TSEQ;
            sH[t] = (tsr[i] - tsr[i + 1]) / 3.0f;
        }
        __syncthreads();

        const float h0 = sH[0], h1 = sH[1], h2 = sH[2], h3 = sH[3];
        const float q0 = 0.5f * h0, q1 = 0.5f * h1, q2 = 0.5f * h2, q3 = 0.5f * h3;
        const float g0 = h0 / 6.0f, g1 = h1 / 6.0f, g2 = h2 / 6.0f, g3 = h3 / 6.0f;

#pragma unroll 1
        for (int sub = 0; sub < 3; ++sub) {
            float s0 = 0.f, s1 = 0.f, s2 = 0.f, s3 = 0.f;
            if (t < LAT) {
                dup4 d = sC[t];
                s0 = lo2(d.lo.x); s1 = lo2(d.lo.y);
                s2 = lo2(d.hi.x); s3 = lo2(d.hi.y);
            }
            float a0 = 0.f, a1 = 0.f, a2 = 0.f, a3 = 0.f;

            // k1
            float4 k = mlp_eval<LAT / 4>(sC, W1, b1c, W2, b2c,
                                         sHid, sPart, t, sA, cA, sB, cB);
            if (t < LAT) {
                a0 = k.x; a1 = k.y; a2 = k.z; a3 = k.w;
                store_dup(&sTmp[t], fmaf(q0, k.x, s0), fmaf(q1, k.y, s1),
                                    fmaf(q2, k.z, s2), fmaf(q3, k.w, s3));
            }
            __syncthreads();

            // k2
            k = mlp_eval<LAT / 4>(sTmp, W1, b1c, W2, b2c,
                                  sHid, sPart, t, sA, cA, sB, cB);
            if (t < LAT) {
                a0 += 2.f * k.x; a1 += 2.f * k.y; a2 += 2.f * k.z; a3 += 2.f * k.w;
                store_dup(&sTmp[t], fmaf(q0, k.x, s0), fmaf(q1, k.y, s1),
                                    fmaf(q2, k.z, s2), fmaf(q3, k.w, s3));
            }
            __syncthreads();

            // k3
            k = mlp_eval<LAT / 4>(sTmp, W1, b1c, W2, b2c,
                                  sHid, sPart, t, sA, cA, sB, cB);
            if (t < LAT) {
                a0 += 2.f * k.x; a1 += 2.f * k.y; a2 += 2.f * k.z; a3 += 2.f * k.w;
                store_dup(&sTmp[t], fmaf(h0, k.x, s0), fmaf(h1, k.y, s1),
                                    fmaf(h2, k.z, s2), fmaf(h3, k.w, s3));
            }
            __syncthreads();

            // k4 + state update
            k = mlp_eval<LAT / 4>(sTmp, W1, b1c, W2, b2c,
                                  sHid, sPart, t, sA, cA, sB, cB);
            if (t < LAT) {
                a0 += k.x; a1 += k.y; a2 += k.z; a3 += k.w;
                store_dup(&sC[t], fmaf(g0, a0, s0), fmaf(g1, a1, s1),
                                  fmaf(g2, a2, s2), fmaf(g3, a3, s3));
            }
            __syncthreads();
        }

        // ---- RNN update: s += rnn(concat(s, x_i)) ----
        {
            float4 o = mlp_eval<KRNN / 4>(sC, Wr1, br1c, Wr2, br2c,
                                          sHid, sPart, t, sA, cA, sB, cB);
            if (t < LAT) {
                dup4 d = sC[t];
                store_dup(&sC[t], lo2(d.lo.x) + o.x, lo2(d.lo.y) + o.y,
                                  lo2(d.hi.x) + o.z, lo2(d.hi.y) + o.w);
            }
            __syncthreads();
        }
    }

    // ---- write final state ----
    if (t < LAT) {
        dup4 d = sC[t];
        out[(row0 + 0) * LAT + t] = lo2(d.lo.x);
        out[(row0 + 1) * LAT + t] = lo2(d.lo.y);
        out[(row0 + 2) * LAT + t] = lo2(d.hi.x);
        out[(row0 + 3) * LAT + t] = lo2(d.hi.y);
    }
}

// ---------------------------------------------------------------------------
extern "C" void kernel_launch(void* const* d_in, const int* in_sizes, int n_in,
                              void* d_out, int out_size)
{
    (void)in_sizes; (void)n_in; (void)out_size;
    const float* dataset    = (const float*)d_in[0];
    const float* timestamps = (const float*)d_in[1];
    const float* W1  = (const float*)d_in[2];
    const float* b1  = (const float*)d_in[3];
    const float* W2  = (const float*)d_in[4];
    const float* b2  = (const float*)d_in[5];
    const float* Wr1 = (const float*)d_in[6];
    const float* br1 = (const float*)d_in[7];
    const float* Wr2 = (const float*)d_in[8];
    const float* br2 = (const float*)d_in[9];
    float* out = (float*)d_out;

    const size_t smem = (KRNN + LAT + HIDD) * sizeof(dup4)
                      + 2048 * sizeof(ulonglong2) + 64;
    static int configured = 0;
    if (!configured) {
        cudaFuncSetAttribute(odernn_kernel,
                             cudaFuncAttributeMaxDynamicSharedMemorySize,
                             (int)smem);
        configured = 1;
    }
    odernn_kernel<<<NCTA, TPB, smem>>>(dataset, timestamps,
                                       W1, b1, W2, b2, Wr1, br1, Wr2, br2, out);
}

// round 11
// speedup vs baseline: 4.0008x; 1.6676x over previous
#include <cuda_runtime.h>
#include <cuda_bf16.h>
#include <stdint.h>
#include <math.h>

// RecognitionODERNN: B=256, T=96, OBS=64, LATENT=256, HID=512, N_SUB=3
//
// 2-CTA clusters x 64 = 128 CTAs (128 SMs), 512 thr/CTA, 4 batch rows per
// cluster. Hidden dim split across the cluster: rank r owns hid cols
// [r*256, r*256+256) (phase A) and K-rows [r*256,...) of phase B. Phase-B
// partials exchanged via DSMEM (double-buffered) with mbarrier
// release/acquire cluster sync. Both CTAs keep identical full state.
// Inner GEMM: dup-pair activations (LDS.128 -> 2 packed rows), LDG.128
// weights (4 cols), fma.rn.f32x2. sPart uses an XOR swizzle so STS.128
// stores and combine loads are bank-conflict-free.

#define TSEQ  96
#define OBSD  64
#define LAT   256
#define HIDD  512
#define KRNN  320
#define ROWS  4
#define TPB   512
#define NCTA  128
#define HHALF 256      // hid cols per CTA
#define NSL   8        // K slices per phase
#define NC    256      // output cols per phase per CTA

typedef unsigned long long u64;
typedef unsigned int u32;

struct dup4 { ulonglong2 lo, hi; };   // (r0,r0),(r1,r1),(r2,r2),(r3,r3)

__device__ __forceinline__ u64 pk2(float x, float y) {
    u64 r; asm("mov.b64 %0, {%1, %2};" : "=l"(r) : "f"(x), "f"(y)); return r;
}
__device__ __forceinline__ void up2(u64 p, float &x, float &y) {
    asm("mov.b64 {%0, %1}, %2;" : "=f"(x), "=f"(y) : "l"(p));
}
__device__ __forceinline__ float lo2(u64 p) {
    float x, y; up2(p, x, y); return x;
}
__device__ __forceinline__ u64 ffma2(u64 a, u64 b, u64 c) {
    u64 d; asm("fma.rn.f32x2 %0, %1, %2, %3;" : "=l"(d) : "l"(a), "l"(b), "l"(c));
    return d;
}
__device__ __forceinline__ u64 fadd2(u64 a, u64 b) {
    u64 d; asm("add.rn.f32x2 %0, %1, %2;" : "=l"(d) : "l"(a), "l"(b)); return d;
}

__device__ __forceinline__ u32 smem_u32(const void *p) {
    u32 a;
    asm("{ .reg .u64 t; cvta.to.shared.u64 t, %1; cvt.u32.u64 %0, t; }"
        : "=r"(a) : "l"(p));
    return a;
}
__device__ __forceinline__ u32 mapa32(u32 addr, u32 rank) {
    u32 r;
    asm("mapa.shared::cluster.u32 %0, %1, %2;" : "=r"(r) : "r"(addr), "r"(rank));
    return r;
}
__device__ __forceinline__ void st_remote16(u32 addr, u64 x, u64 y) {
    asm volatile("st.shared::cluster.u64 [%0], %1;" :: "r"(addr), "l"(x) : "memory");
    asm volatile("st.shared::cluster.u64 [%0], %1;" :: "r"(addr + 8), "l"(y) : "memory");
}
__device__ __forceinline__ void arrive_remote(u32 rmbar) {
    asm volatile("mbarrier.arrive.release.cluster.shared::cluster.b64 _, [%0];"
                 :: "r"(rmbar) : "memory");
}
__device__ __forceinline__ void wait_parity_cluster(u32 mbar, u32 ph) {
    asm volatile(
        "{\n\t"
        ".reg .pred P;\n"
        "WLOOP%=:\n\t"
        "mbarrier.try_wait.parity.acquire.cluster.shared::cta.b64 P, [%0], %1;\n\t"
        "@!P bra WLOOP%=;\n\t"
        "}"
        :: "r"(mbar), "r"(ph) : "memory");
}
__device__ __forceinline__ void cluster_sync() {
    asm volatile("barrier.cluster.arrive.aligned;" ::: "memory");
    asm volatile("barrier.cluster.wait.aligned;" ::: "memory");
}

// XOR swizzle: makes STS.128 stores (4 consecutive cols/thread) and combine
// loads (1 col/thread) conflict-free within each 8-thread 128-bit phase.
__device__ __forceinline__ int swz(int c) { return c ^ ((c >> 2) & 7); }

__device__ __forceinline__ void store_dup(dup4 *dst, float v0, float v1,
                                          float v2, float v3)
{
    dup4 d;
    d.lo.x = pk2(v0, v0); d.lo.y = pk2(v1, v1);
    d.hi.x = pk2(v2, v2); d.hi.y = pk2(v3, v3);
    *dst = d;
}

// ---------------------------------------------------------------------------
// thread computes 4 output columns [c0, c0+4) over K-slice s (KSPAN rows).
// ---------------------------------------------------------------------------
template <int KSPAN, int WSTRIDE>
__device__ __forceinline__ void gemm_slice(const dup4 *__restrict__ in,
                                           const float *__restrict__ W,
                                           ulonglong2 *__restrict__ sPart,
                                           int s, int c0)
{
    const dup4 *ip = in + s * KSPAN;
    const float *wp = W + (size_t)(s * KSPAN) * WSTRIDE + c0;

    u64 a0 = 0, a1 = 0, a2 = 0, a3 = 0;   // cols (c0, c0+1), rows 0..3
    u64 b0 = 0, b1 = 0, b2 = 0, b3 = 0;   // cols (c0+2, c0+3), rows 0..3
#pragma unroll 8
    for (int k = 0; k < KSPAN; ++k) {
        dup4 a = ip[k];
        ulonglong2 w = *reinterpret_cast<const ulonglong2 *>(wp + (size_t)k * WSTRIDE);
        a0 = ffma2(a.lo.x, w.x, a0);  b0 = ffma2(a.lo.x, w.y, b0);
        a1 = ffma2(a.lo.y, w.x, a1);  b1 = ffma2(a.lo.y, w.y, b1);
        a2 = ffma2(a.hi.x, w.x, a2);  b2 = ffma2(a.hi.x, w.y, b2);
        a3 = ffma2(a.hi.y, w.x, a3);  b3 = ffma2(a.hi.y, w.y, b3);
    }
    float f00, f01, f10, f11, f20, f21, f30, f31;
    float g00, g01, g10, g11, g20, g21, g30, g31;
    up2(a0, f00, f01); up2(a1, f10, f11); up2(a2, f20, f21); up2(a3, f30, f31);
    up2(b0, g00, g01); up2(b1, g10, g11); up2(b2, g20, g21); up2(b3, g30, g31);
    ulonglong2 *base = sPart + s * NC;
    ulonglong2 v;
    v.x = pk2(f00, f10); v.y = pk2(f20, f30); base[swz(c0 + 0)] = v;
    v.x = pk2(f01, f11); v.y = pk2(f21, f31); base[swz(c0 + 1)] = v;
    v.x = pk2(g00, g10); v.y = pk2(g20, g30); base[swz(c0 + 2)] = v;
    v.x = pk2(g01, g11); v.y = pk2(g21, g31); base[swz(c0 + 3)] = v;
}

// Sum 8 partial slices for column c (+ bias) -> ((r0,r1),(r2,r3))
__device__ __forceinline__ ulonglong2 combine8(const ulonglong2 *__restrict__ sPart,
                                               int c, float bias)
{
    const int sc = swz(c);
    ulonglong2 p0 = sPart[sc];
    u64 sx = p0.x, sy = p0.y;
#pragma unroll
    for (int s = 1; s < NSL; ++s) {
        ulonglong2 p = sPart[s * NC + sc];
        sx = fadd2(sx, p.x);
        sy = fadd2(sy, p.y);
    }
    u64 bb = pk2(bias, bias);
    ulonglong2 r; r.x = fadd2(sx, bb); r.y = fadd2(sy, bb);
    return r;
}

// ---------------------------------------------------------------------------
// One full MLP eval with cross-CTA K reduction on phase B.
// All TPB threads call this. Returns out column t (rows 0..3) for t < NC.
// ---------------------------------------------------------------------------
template <int KSA>
__device__ __forceinline__ float4 mlp_eval(
    const dup4 *__restrict__ in,
    const float *__restrict__ Wa, float ba,
    const float *__restrict__ Wb, float bb,
    dup4 *__restrict__ sHid, ulonglong2 *__restrict__ sPart,
    ulonglong2 *__restrict__ sPeer,
    u32 peerBufAddr, u32 mbarAddr, u32 mbarPeerAddr,
    int t, int s, int c0, int &x)
{
    gemm_slice<KSA, HIDD>(in, Wa, sPart, s, c0);
    __syncthreads();
    if (t < NC) {   // combine A + tanh -> local sHid
        ulonglong2 h = combine8(sPart, t, ba);
        float u0, u1, u2, u3;
        up2(h.x, u0, u1); up2(h.y, u2, u3);
        store_dup(&sHid[t], tanhf(u0), tanhf(u1), tanhf(u2), tanhf(u3));
    }
    __syncthreads();
    gemm_slice<HHALF / NSL, LAT>(sHid, Wb, sPart, s, c0);
    __syncthreads();

    float4 res = make_float4(0.f, 0.f, 0.f, 0.f);
    const int buf = x & 1;
    if (t < NC) {
        ulonglong2 p = combine8(sPart, t, 0.f);          // local K-half partial
        // send my partial to peer's sPeer[buf][t], then release-arrive on
        // peer's mbar; wait for peer's 256 arrivals on mine (acquire).
        st_remote16(peerBufAddr + (u32)(buf * NC + t) * 16u, p.x, p.y);
        arrive_remote(mbarPeerAddr);
        wait_parity_cluster(mbarAddr, (u32)buf);
        ulonglong2 q = sPeer[buf * NC + t];
        u64 bb2 = pk2(bb, bb);
        u64 sx = fadd2(fadd2(p.x, q.x), bb2);
        u64 sy = fadd2(fadd2(p.y, q.y), bb2);
        up2(sx, res.x, res.y);
        up2(sy, res.z, res.w);
    }
    x++;
    return res;
}

// ---------------------------------------------------------------------------
__global__ void __launch_bounds__(TPB, 1) __cluster_dims__(2, 1, 1)
odernn_kernel(const float *__restrict__ dataset,    // [B, T, OBS]
              const float *__restrict__ timestamps, // [B, T]
              const float *__restrict__ W1,  const float *__restrict__ b1,
              const float *__restrict__ W2,  const float *__restrict__ b2,
              const float *__restrict__ Wr1, const float *__restrict__ br1,
              const float *__restrict__ Wr2, const float *__restrict__ br2,
              float *__restrict__ out)               // [B, LAT]
{
    extern __shared__ char smem[];
    dup4       *sC    = reinterpret_cast<dup4 *>(smem);               // [320]
    dup4       *sTmp  = sC + KRNN;                                    // [256]
    dup4       *sHid  = sTmp + LAT;                                   // [256]
    ulonglong2 *sPart = reinterpret_cast<ulonglong2 *>(sHid + HHALF); // [8*256]
    ulonglong2 *sPeer = sPart + NSL * NC;                             // [2*256]
    float      *sH    = reinterpret_cast<float *>(sPeer + 2 * NC);    // [4]
    u64        *mbarp = reinterpret_cast<u64 *>(sH + 4);              // [1]

    const int t = threadIdx.x;
    u32 rank;
    asm("mov.u32 %0, %%cluster_ctarank;" : "=r"(rank));
    const u32 peerRank = rank ^ 1u;
    const int row0  = (blockIdx.x >> 1) * ROWS;
    const int hbase = (int)rank * HHALF;

    const int s  = t >> 6;            // K-slice 0..7
    const int c0 = 4 * (t & 63);      // column group

    const u32 mbarAddr     = smem_u32(mbarp);
    const u32 mbarPeerAddr = mapa32(mbarAddr, peerRank);
    const u32 peerBufAddr  = mapa32(smem_u32(sPeer), peerRank);

    // weight slices for this rank
    const float *W1r  = W1  + hbase;                    // cols [hbase, +256)
    const float *Wr1r = Wr1 + hbase;
    const float *W2r  = W2  + (size_t)hbase * LAT;      // K-rows [hbase, +256)
    const float *Wr2r = Wr2 + (size_t)hbase * LAT;

    const float baO = (t < NC) ? b1[hbase + t]  : 0.f;  // phase-A bias (ODE)
    const float baR = (t < NC) ? br1[hbase + t] : 0.f;  // phase-A bias (RNN)
    const float bbO = (t < NC) ? b2[t]  : 0.f;          // phase-B bias (ODE)
    const float bbR = (t < NC) ? br2[t] : 0.f;          // phase-B bias (RNN)

    // ---- init: mbar, state = 0, x_{T-1} ----
    if (t == 0)
        asm volatile("mbarrier.init.shared.b64 [%0], %1;"
                     :: "r"(mbarAddr), "r"(NC) : "memory");
    if (t < LAT) store_dup(&sC[t], 0.f, 0.f, 0.f, 0.f);
    if (t < LAT) {
        const int cc = t & (OBSD - 1);
        const int r  = t >> 6;
        float v = dataset[((row0 + r) * TSEQ + (TSEQ - 1)) * OBSD + cc];
        reinterpret_cast<u64 *>(&sC[LAT + cc])[r] = pk2(v, v);
    }
    __syncthreads();
    cluster_sync();   // mbar + state visible cluster-wide before first exchange

    int x = 0;        // exchange counter (uniform across both CTAs)

    // ---- initial RNN update: s += rnn(concat(s, x_{T-1})) ----
    {
        float4 o = mlp_eval<KRNN / NSL>(sC, Wr1r, baR, Wr2r, bbR,
                                        sHid, sPart, sPeer,
                                        peerBufAddr, mbarAddr, mbarPeerAddr,
                                        t, s, c0, x);
        if (t < NC) {
            dup4 d = sC[t];
            store_dup(&sC[t], lo2(d.lo.x) + o.x, lo2(d.lo.y) + o.y,
                              lo2(d.hi.x) + o.z, lo2(d.hi.y) + o.w);
        }
        __syncthreads();
    }

    // ---- reverse-time scan: i = T-2 .. 0 ----
    for (int i = TSEQ - 2; i >= 0; --i) {
        if (t < LAT) {
            const int cc = t & (OBSD - 1);
            const int r  = t >> 6;
            float v = dataset[((row0 + r) * TSEQ + i) * OBSD + cc];
            reinterpret_cast<u64 *>(&sC[LAT + cc])[r] = pk2(v, v);
        }
        if (t < ROWS) {
            const float *tsr = timestamps + (row0 + t) * TSEQ;
            sH[t] = (tsr[i] - tsr[i + 1]) / 3.0f;
        }
        __syncthreads();

        const float h0 = sH[0], h1 = sH[1], h2 = sH[2], h3 = sH[3];
        const float q0 = 0.5f * h0, q1 = 0.5f * h1, q2 = 0.5f * h2, q3 = 0.5f * h3;
        const float g0 = h0 / 6.0f, g1 = h1 / 6.0f, g2 = h2 / 6.0f, g3 = h3 / 6.0f;

#pragma unroll 1
        for (int sub = 0; sub < 3; ++sub) {
            float s0 = 0.f, s1 = 0.f, s2 = 0.f, s3 = 0.f;
            if (t < NC) {
                dup4 d = sC[t];
                s0 = lo2(d.lo.x); s1 = lo2(d.lo.y);
                s2 = lo2(d.hi.x); s3 = lo2(d.hi.y);
            }
            float a0 = 0.f, a1 = 0.f, a2 = 0.f, a3 = 0.f;

            // k1
            float4 k = mlp_eval<LAT / NSL>(sC, W1r, baO, W2r, bbO,
                                           sHid, sPart, sPeer,
                                           peerBufAddr, mbarAddr, mbarPeerAddr,
                                           t, s, c0, x);
            if (t < NC) {
                a0 = k.x; a1 = k.y; a2 = k.z; a3 = k.w;
                store_dup(&sTmp[t], fmaf(q0, k.x, s0), fmaf(q1, k.y, s1),
                                    fmaf(q2, k.z, s2), fmaf(q3, k.w, s3));
            }
            __syncthreads();

            // k2
            k = mlp_eval<LAT / NSL>(sTmp, W1r, baO, W2r, bbO,
                                    sHid, sPart, sPeer,
                                    peerBufAddr, mbarAddr, mbarPeerAddr,
                                    t, s, c0, x);
            if (t < NC) {
                a0 += 2.f * k.x; a1 += 2.f * k.y; a2 += 2.f * k.z; a3 += 2.f * k.w;
                store_dup(&sTmp[t], fmaf(q0, k.x, s0), fmaf(q1, k.y, s1),
                                    fmaf(q2, k.z, s2), fmaf(q3, k.w, s3));
            }
            __syncthreads();

            // k3
            k = mlp_eval<LAT / NSL>(sTmp, W1r, baO, W2r, bbO,
                                    sHid, sPart, sPeer,
                                    peerBufAddr, mbarAddr, mbarPeerAddr,
                                    t, s, c0, x);
            if (t < NC) {
                a0 += 2.f * k.x; a1 += 2.f * k.y; a2 += 2.f * k.z; a3 += 2.f * k.w;
                store_dup(&sTmp[t], fmaf(h0, k.x, s0), fmaf(h1, k.y, s1),
                                    fmaf(h2, k.z, s2), fmaf(h3, k.w, s3));
            }
            __syncthreads();

            // k4 + state update
            k = mlp_eval<LAT / NSL>(sTmp, W1r, baO, W2r, bbO,
                                    sHid, sPart, sPeer,
                                    peerBufAddr, mbarAddr, mbarPeerAddr,
                                    t, s, c0, x);
            if (t < NC) {
                a0 += k.x; a1 += k.y; a2 += k.z; a3 += k.w;
                store_dup(&sC[t], fmaf(g0, a0, s0), fmaf(g1, a1, s1),
                                  fmaf(g2, a2, s2), fmaf(g3, a3, s3));
            }
            __syncthreads();
        }

        // ---- RNN update: s += rnn(concat(s, x_i)) ----
        {
            float4 o = mlp_eval<KRNN / NSL>(sC, Wr1r, baR, Wr2r, bbR,
                                            sHid, sPart, sPeer,
                                            peerBufAddr, mbarAddr, mbarPeerAddr,
                                            t, s, c0, x);
            if (t < NC) {
                dup4 d = sC[t];
                store_dup(&sC[t], lo2(d.lo.x) + o.x, lo2(d.lo.y) + o.y,
                                  lo2(d.hi.x) + o.z, lo2(d.hi.y) + o.w);
            }
            __syncthreads();
        }
    }

    // ---- write final state (rank 0 only; both CTAs hold identical state) ----
    if (rank == 0 && t < NC) {
        dup4 d = sC[t];
        out[(row0 + 0) * LAT + t] = lo2(d.lo.x);
        out[(row0 + 1) * LAT + t] = lo2(d.lo.y);
        out[(row0 + 2) * LAT + t] = lo2(d.hi.x);
        out[(row0 + 3) * LAT + t] = lo2(d.hi.y);
    }

    cluster_sync();   // no CTA exits while peer traffic may be in flight
}

// ---------------------------------------------------------------------------
extern "C" void kernel_launch(void* const* d_in, const int* in_sizes, int n_in,
                              void* d_out, int out_size)
{
    (void)in_sizes; (void)n_in; (void)out_size;
    const float* dataset    = (const float*)d_in[0];
    const float* timestamps = (const float*)d_in[1];
    const float* W1  = (const float*)d_in[2];
    const float* b1  = (const float*)d_in[3];
    const float* W2  = (const float*)d_in[4];
    const float* b2  = (const float*)d_in[5];
    const float* Wr1 = (const float*)d_in[6];
    const float* br1 = (const float*)d_in[7];
    const float* Wr2 = (const float*)d_in[8];
    const float* br2 = (const float*)d_in[9];
    float* out = (float*)d_out;

    const size_t smem = (KRNN + LAT + HHALF) * sizeof(dup4)
                      + (NSL * NC + 2 * NC) * sizeof(ulonglong2)
                      + 4 * sizeof(float) + 2 * sizeof(u64) + 64;
    static int configured = 0;
    if (!configured) {
        cudaFuncSetAttribute(odernn_kernel,
                             cudaFuncAttributeMaxDynamicSharedMemorySize,
                             (int)smem);
        configured = 1;
    }
    odernn_kernel<<<NCTA, TPB, smem>>>(dataset, timestamps,
                                       W1, b1, W2, b2, Wr1, br1, Wr2, br2, out);
}

// round 12
// speedup vs baseline: 4.8391x; 1.2095x over previous
#include <cuda_runtime.h>
#include <cuda_bf16.h>
#include <stdint.h>
#include <math.h>

// RecognitionODERNN: B=256, T=96, OBS=64, LATENT=256, HID=512, N_SUB=3
//
// 2-CTA clusters x 64 = 128 CTAs (128 SMs), 512 thr/CTA, 4 batch rows per
// cluster. Hidden dim split across the cluster; phase-B K-half partials
// exchanged via DSMEM (double-buffered) with per-thread mbarrier
// release/acquire. Both CTAs keep identical full state.
//
// R12 change vs R11: activations stored as packed row-pairs (r0,r1),(r2,r3)
// (ONE LDS.128 per k, no duplication); weights duplicated with MOV64s on the
// idle ALU pipe. Accumulators are per-column row-pairs -> no 4x4 transpose,
// direct sPart stores. Halves LDS phases and hid/state STS bytes.

#define TSEQ  96
#define OBSD  64
#define LAT   256
#define HIDD  512
#define KRNN  320
#define ROWS  4
#define TPB   512
#define NCTA  128
#define HHALF 256      // hid cols per CTA
#define NSL   8        // K slices per phase
#define NC    256      // output cols per phase per CTA

typedef unsigned long long u64;
typedef unsigned int u32;

__device__ __forceinline__ u64 pk2(float x, float y) {
    u64 r; asm("mov.b64 %0, {%1, %2};" : "=l"(r) : "f"(x), "f"(y)); return r;
}
__device__ __forceinline__ void up2(u64 p, float &x, float &y) {
    asm("mov.b64 {%0, %1}, %2;" : "=f"(x), "=f"(y) : "l"(p));
}
__device__ __forceinline__ u64 ffma2(u64 a, u64 b, u64 c) {
    u64 d; asm("fma.rn.f32x2 %0, %1, %2, %3;" : "=l"(d) : "l"(a), "l"(b), "l"(c));
    return d;
}
__device__ __forceinline__ u64 fadd2(u64 a, u64 b) {
    u64 d; asm("add.rn.f32x2 %0, %1, %2;" : "=l"(d) : "l"(a), "l"(b)); return d;
}

__device__ __forceinline__ u32 smem_u32(const void *p) {
    u32 a;
    asm("{ .reg .u64 t; cvta.to.shared.u64 t, %1; cvt.u32.u64 %0, t; }"
        : "=r"(a) : "l"(p));
    return a;
}
__device__ __forceinline__ u32 mapa32(u32 addr, u32 rank) {
    u32 r;
    asm("mapa.shared::cluster.u32 %0, %1, %2;" : "=r"(r) : "r"(addr), "r"(rank));
    return r;
}
__device__ __forceinline__ void st_remote16(u32 addr, u64 x, u64 y) {
    asm volatile("st.shared::cluster.u64 [%0], %1;" :: "r"(addr), "l"(x) : "memory");
    asm volatile("st.shared::cluster.u64 [%0], %1;" :: "r"(addr + 8), "l"(y) : "memory");
}
__device__ __forceinline__ void arrive_remote(u32 rmbar) {
    asm volatile("mbarrier.arrive.release.cluster.shared::cluster.b64 _, [%0];"
                 :: "r"(rmbar) : "memory");
}
__device__ __forceinline__ void wait_parity_cluster(u32 mbar, u32 ph) {
    asm volatile(
        "{\n\t"
        ".reg .pred P;\n"
        "WLOOP%=:\n\t"
        "mbarrier.try_wait.parity.acquire.cluster.shared::cta.b64 P, [%0], %1;\n\t"
        "@!P bra WLOOP%=;\n\t"
        "}"
        :: "r"(mbar), "r"(ph) : "memory");
}
__device__ __forceinline__ void cluster_sync() {
    asm volatile("barrier.cluster.arrive.aligned;" ::: "memory");
    asm volatile("barrier.cluster.wait.aligned;" ::: "memory");
}

// XOR swizzle for sPart: conflict-free STS.128 / combine loads.
__device__ __forceinline__ int swz(int c) { return c ^ ((c >> 2) & 7); }

// store packed row-pairs (one STS.128)
__device__ __forceinline__ void store_p(ulonglong2 *dst, float v0, float v1,
                                        float v2, float v3)
{
    ulonglong2 d;
    d.x = pk2(v0, v1);
    d.y = pk2(v2, v3);
    *dst = d;
}

// ---------------------------------------------------------------------------
// thread computes 4 output columns [c0, c0+4) over K-slice s (KSPAN rows).
// in: packed row-pairs; per k: 1 LDS.128 + 1 LDG.128 + 4 MOV64 + 8 FFMA2.
// Accumulators are per-column row-pairs -> direct sPart stores, no transpose.
// ---------------------------------------------------------------------------
template <int KSPAN, int WSTRIDE>
__device__ __forceinline__ void gemm_slice(const ulonglong2 *__restrict__ in,
                                           const float *__restrict__ W,
                                           ulonglong2 *__restrict__ sPart,
                                           int s, int c0)
{
    const ulonglong2 *ip = in + s * KSPAN;
    const float *wp = W + (size_t)(s * KSPAN) * WSTRIDE + c0;

    u64 a00 = 0, a01 = 0;   // col c0  : (r0,r1), (r2,r3)
    u64 a10 = 0, a11 = 0;   // col c0+1
    u64 a20 = 0, a21 = 0;   // col c0+2
    u64 a30 = 0, a31 = 0;   // col c0+3
#pragma unroll 8
    for (int k = 0; k < KSPAN; ++k) {
        ulonglong2 a = ip[k];                  // ONE LDS.128: (r0,r1),(r2,r3)
        ulonglong2 w = *reinterpret_cast<const ulonglong2 *>(wp + (size_t)k * WSTRIDE);
        float w0, w1, w2, w3;
        up2(w.x, w0, w1); up2(w.y, w2, w3);    // register renames (free)
        u64 W0 = pk2(w0, w0), W1 = pk2(w1, w1);    // ALU-pipe dups
        u64 W2 = pk2(w2, w2), W3 = pk2(w3, w3);
        a00 = ffma2(a.x, W0, a00);  a01 = ffma2(a.y, W0, a01);
        a10 = ffma2(a.x, W1, a10);  a11 = ffma2(a.y, W1, a11);
        a20 = ffma2(a.x, W2, a20);  a21 = ffma2(a.y, W2, a21);
        a30 = ffma2(a.x, W3, a30);  a31 = ffma2(a.y, W3, a31);
    }
    ulonglong2 *base = sPart + s * NC;
    ulonglong2 v;
    v.x = a00; v.y = a01; base[swz(c0 + 0)] = v;
    v.x = a10; v.y = a11; base[swz(c0 + 1)] = v;
    v.x = a20; v.y = a21; base[swz(c0 + 2)] = v;
    v.x = a30; v.y = a31; base[swz(c0 + 3)] = v;
}

// Sum 8 partial slices for column c (+ bias) -> ((r0,r1),(r2,r3))
__device__ __forceinline__ ulonglong2 combine8(const ulonglong2 *__restrict__ sPart,
                                               int c, float bias)
{
    const int sc = swz(c);
    ulonglong2 p0 = sPart[sc];
    u64 sx = p0.x, sy = p0.y;
#pragma unroll
    for (int s = 1; s < NSL; ++s) {
        ulonglong2 p = sPart[s * NC + sc];
        sx = fadd2(sx, p.x);
        sy = fadd2(sy, p.y);
    }
    u64 bb = pk2(bias, bias);
    ulonglong2 r; r.x = fadd2(sx, bb); r.y = fadd2(sy, bb);
    return r;
}

// ---------------------------------------------------------------------------
// One full MLP eval with cross-CTA K reduction on phase B.
// ---------------------------------------------------------------------------
template <int KSA>
__device__ __forceinline__ float4 mlp_eval(
    const ulonglong2 *__restrict__ in,
    const float *__restrict__ Wa, float ba,
    const float *__restrict__ Wb, float bb,
    ulonglong2 *__restrict__ sHid, ulonglong2 *__restrict__ sPart,
    ulonglong2 *__restrict__ sPeer,
    u32 peerBufAddr, u32 mbarAddr, u32 mbarPeerAddr,
    int t, int s, int c0, int &x)
{
    gemm_slice<KSA, HIDD>(in, Wa, sPart, s, c0);
    __syncthreads();
    if (t < NC) {   // combine A + tanh -> local sHid
        ulonglong2 h = combine8(sPart, t, ba);
        float u0, u1, u2, u3;
        up2(h.x, u0, u1); up2(h.y, u2, u3);
        store_p(&sHid[t], tanhf(u0), tanhf(u1), tanhf(u2), tanhf(u3));
    }
    __syncthreads();
    gemm_slice<HHALF / NSL, LAT>(sHid, Wb, sPart, s, c0);
    __syncthreads();

    float4 res = make_float4(0.f, 0.f, 0.f, 0.f);
    const int buf = x & 1;
    if (t < NC) {
        ulonglong2 p = combine8(sPart, t, 0.f);          // local K-half partial
        st_remote16(peerBufAddr + (u32)(buf * NC + t) * 16u, p.x, p.y);
        arrive_remote(mbarPeerAddr);
        wait_parity_cluster(mbarAddr, (u32)buf);
        ulonglong2 q = sPeer[buf * NC + t];
        u64 bb2 = pk2(bb, bb);
        u64 sx = fadd2(fadd2(p.x, q.x), bb2);
        u64 sy = fadd2(fadd2(p.y, q.y), bb2);
        up2(sx, res.x, res.y);
        up2(sy, res.z, res.w);
    }
    x++;
    return res;
}

// ---------------------------------------------------------------------------
__global__ void __launch_bounds__(TPB, 1) __cluster_dims__(2, 1, 1)
odernn_kernel(const float *__restrict__ dataset,    // [B, T, OBS]
              const float *__restrict__ timestamps, // [B, T]
              const float *__restrict__ W1,  const float *__restrict__ b1,
              const float *__restrict__ W2,  const float *__restrict__ b2,
              const float *__restrict__ Wr1, const float *__restrict__ br1,
              const float *__restrict__ Wr2, const float *__restrict__ br2,
              float *__restrict__ out)               // [B, LAT]
{
    extern __shared__ char smem[];
    ulonglong2 *sC    = reinterpret_cast<ulonglong2 *>(smem);         // [320]
    ulonglong2 *sTmp  = sC + KRNN;                                    // [256]
    ulonglong2 *sHid  = sTmp + LAT;                                   // [256]
    ulonglong2 *sPart = sHid + HHALF;                                 // [8*256]
    ulonglong2 *sPeer = sPart + NSL * NC;                             // [2*256]
    float      *sH    = reinterpret_cast<float *>(sPeer + 2 * NC);    // [4]
    u64        *mbarp = reinterpret_cast<u64 *>(sH + 4);              // [1]

    const int t = threadIdx.x;
    u32 rank;
    asm("mov.u32 %0, %%cluster_ctarank;" : "=r"(rank));
    const u32 peerRank = rank ^ 1u;
    const int row0  = (blockIdx.x >> 1) * ROWS;
    const int hbase = (int)rank * HHALF;

    const int s  = t >> 6;            // K-slice 0..7
    const int c0 = 4 * (t & 63);      // column group

    const u32 mbarAddr     = smem_u32(mbarp);
    const u32 mbarPeerAddr = mapa32(mbarAddr, peerRank);
    const u32 peerBufAddr  = mapa32(smem_u32(sPeer), peerRank);

    // weight slices for this rank
    const float *W1r  = W1  + hbase;                    // cols [hbase, +256)
    const float *Wr1r = Wr1 + hbase;
    const float *W2r  = W2  + (size_t)hbase * LAT;      // K-rows [hbase, +256)
    const float *Wr2r = Wr2 + (size_t)hbase * LAT;

    const float baO = (t < NC) ? b1[hbase + t]  : 0.f;
    const float baR = (t < NC) ? br1[hbase + t] : 0.f;
    const float bbO = (t < NC) ? b2[t]  : 0.f;
    const float bbR = (t < NC) ? br2[t] : 0.f;

    // ---- init: mbar, state = 0, x_{T-1} ----
    if (t == 0)
        asm volatile("mbarrier.init.shared.b64 [%0], %1;"
                     :: "r"(mbarAddr), "r"(NC) : "memory");
    if (t < LAT) store_p(&sC[t], 0.f, 0.f, 0.f, 0.f);
    if (t < LAT) {
        const int cc = t & (OBSD - 1);
        const int r  = t >> 6;     // entry = 4 floats r0..r3 in order
        float v = dataset[((row0 + r) * TSEQ + (TSEQ - 1)) * OBSD + cc];
        reinterpret_cast<float *>(&sC[LAT + cc])[r] = v;
    }
    __syncthreads();
    cluster_sync();   // mbar + state visible cluster-wide before first exchange

    int x = 0;        // exchange counter (uniform across both CTAs)

    // ---- initial RNN update: s += rnn(concat(s, x_{T-1})) ----
    {
        float4 o = mlp_eval<KRNN / NSL>(sC, Wr1r, baR, Wr2r, bbR,
                                        sHid, sPart, sPeer,
                                        peerBufAddr, mbarAddr, mbarPeerAddr,
                                        t, s, c0, x);
        if (t < NC) {
            ulonglong2 d = sC[t];
            float s0, s1, s2, s3;
            up2(d.x, s0, s1); up2(d.y, s2, s3);
            store_p(&sC[t], s0 + o.x, s1 + o.y, s2 + o.z, s3 + o.w);
        }
        __syncthreads();
    }

    // ---- reverse-time scan: i = T-2 .. 0 ----
    for (int i = TSEQ - 2; i >= 0; --i) {
        if (t < LAT) {
            const int cc = t & (OBSD - 1);
            const int r  = t >> 6;
            float v = dataset[((row0 + r) * TSEQ + i) * OBSD + cc];
            reinterpret_cast<float *>(&sC[LAT + cc])[r] = v;
        }
        if (t < ROWS) {
            const float *tsr = timestamps + (row0 + t) * TSEQ;
            sH[t] = (tsr[i] - tsr[i + 1]) / 3.0f;
        }
        __syncthreads();

        const float h0 = sH[0], h1 = sH[1], h2 = sH[2], h3 = sH[3];
        const float q0 = 0.5f * h0, q1 = 0.5f * h1, q2 = 0.5f * h2, q3 = 0.5f * h3;
        const float g0 = h0 / 6.0f, g1 = h1 / 6.0f, g2 = h2 / 6.0f, g3 = h3 / 6.0f;

#pragma unroll 1
        for (int sub = 0; sub < 3; ++sub) {
            float s0 = 0.f, s1 = 0.f, s2 = 0.f, s3 = 0.f;
            if (t < NC) {
                ulonglong2 d = sC[t];
                up2(d.x, s0, s1); up2(d.y, s2, s3);
            }
            float a0 = 0.f, a1 = 0.f, a2 = 0.f, a3 = 0.f;

            // k1
            float4 k = mlp_eval<LAT / NSL>(sC, W1r, baO, W2r, bbO,
                                           sHid, sPart, sPeer,
                                           peerBufAddr, mbarAddr, mbarPeerAddr,
                                           t, s, c0, x);
            if (t < NC) {
                a0 = k.x; a1 = k.y; a2 = k.z; a3 = k.w;
                store_p(&sTmp[t], fmaf(q0, k.x, s0), fmaf(q1, k.y, s1),
                                  fmaf(q2, k.z, s2), fmaf(q3, k.w, s3));
            }
            __syncthreads();

            // k2
            k = mlp_eval<LAT / NSL>(sTmp, W1r, baO, W2r, bbO,
                                    sHid, sPart, sPeer,
                                    peerBufAddr, mbarAddr, mbarPeerAddr,
                                    t, s, c0, x);
            if (t < NC) {
                a0 += 2.f * k.x; a1 += 2.f * k.y; a2 += 2.f * k.z; a3 += 2.f * k.w;
                store_p(&sTmp[t], fmaf(q0, k.x, s0), fmaf(q1, k.y, s1),
                                  fmaf(q2, k.z, s2), fmaf(q3, k.w, s3));
            }
            __syncthreads();

            // k3
            k = mlp_eval<LAT / NSL>(sTmp, W1r, baO, W2r, bbO,
                                    sHid, sPart, sPeer,
                                    peerBufAddr, mbarAddr, mbarPeerAddr,
                                    t, s, c0, x);
            if (t < NC) {
                a0 += 2.f * k.x; a1 += 2.f * k.y; a2 += 2.f * k.z; a3 += 2.f * k.w;
                store_p(&sTmp[t], fmaf(h0, k.x, s0), fmaf(h1, k.y, s1),
                                  fmaf(h2, k.z, s2), fmaf(h3, k.w, s3));
            }
            __syncthreads();

            // k4 + state update
            k = mlp_eval<LAT / NSL>(sTmp, W1r, baO, W2r, bbO,
                                    sHid, sPart, sPeer,
                                    peerBufAddr, mbarAddr, mbarPeerAddr,
                                    t, s, c0, x);
            if (t < NC) {
                a0 += k.x; a1 += k.y; a2 += k.z; a3 += k.w;
                store_p(&sC[t], fmaf(g0, a0, s0), fmaf(g1, a1, s1),
                                fmaf(g2, a2, s2), fmaf(g3, a3, s3));
            }
            __syncthreads();
        }

        // ---- RNN update: s += rnn(concat(s, x_i)) ----
        {
            float4 o = mlp_eval<KRNN / NSL>(sC, Wr1r, baR, Wr2r, bbR,
                                            sHid, sPart, sPeer,
                                            peerBufAddr, mbarAddr, mbarPeerAddr,
                                            t, s, c0, x);
            if (t < NC) {
                ulonglong2 d = sC[t];
                float s0, s1, s2, s3;
                up2(d.x, s0, s1); up2(d.y, s2, s3);
                store_p(&sC[t], s0 + o.x, s1 + o.y, s2 + o.z, s3 + o.w);
            }
            __syncthreads();
        }
    }

    // ---- write final state (rank 0 only) ----
    if (rank == 0 && t < NC) {
        ulonglong2 d = sC[t];
        float s0, s1, s2, s3;
        up2(d.x, s0, s1); up2(d.y, s2, s3);
        out[(row0 + 0) * LAT + t] = s0;
        out[(row0 + 1) * LAT + t] = s1;
        out[(row0 + 2) * LAT + t] = s2;
        out[(row0 + 3) * LAT + t] = s3;
    }

    cluster_sync();   // no CTA exits while peer traffic may be in flight
}

// ---------------------------------------------------------------------------
extern "C" void kernel_launch(void* const* d_in, const int* in_sizes, int n_in,
                              void* d_out, int out_size)
{
    (void)in_sizes; (void)n_in; (void)out_size;
    const float* dataset    = (const float*)d_in[0];
    const float* timestamps = (const float*)d_in[1];
    const float* W1  = (const float*)d_in[2];
    const float* b1  = (const float*)d_in[3];
    const float* W2  = (const float*)d_in[4];
    const float* b2  = (const float*)d_in[5];
    const float* Wr1 = (const float*)d_in[6];
    const float* br1 = (const float*)d_in[7];
    const float* Wr2 = (const float*)d_in[8];
    const float* br2 = (const float*)d_in[9];
    float* out = (float*)d_out;

    const size_t smem = (KRNN + LAT + HHALF) * sizeof(ulonglong2)
                      + (NSL * NC + 2 * NC) * sizeof(ulonglong2)
                      + 4 * sizeof(float) + 2 * sizeof(u64) + 64;
    static int configured = 0;
    if (!configured) {
        cudaFuncSetAttribute(odernn_kernel,
                             cudaFuncAttributeMaxDynamicSharedMemorySize,
                             (int)smem);
        configured = 1;
    }
    odernn_kernel<<<NCTA, TPB, smem>>>(dataset, timestamps,
                                       W1, b1, W2, b2, Wr1, br1, Wr2, br2, out);
}